// round 6
// baseline (speedup 1.0000x reference)
#include <cuda_runtime.h>
#include <cuda_bf16.h>
#include <cstdint>

// T=8 tables, N=500000 rows/table, D=64, B=16384 bags/table, L=20.
// indices [T*B*L] int32 (global row ids), offsets [T*B] int32,
// weights [T*N*D] f32. Output [B, T*D] f32.
//
// Persistent kernel: one wave of CTAs; each warp grid-strides over bags.
// Per bag: lanes 0-15 -> even rows, lanes 16-31 -> odd rows, float4/lane
// => 512B per gather instruction. Gathers via cp.async.cg into a 6-deep
// smem ring (zero register residency in flight). Next bag's offsets and
// index vector are prefetched during the current bag's gather drain so
// the dependent index-load chain never exposes latency.

#define EMB_D 64
#define EMB_T 8
#define STAGES 6
#define WPB 8          // warps per block
#define PERSIST_BLOCKS 1216   // 152 SMs * 8 blocks

__device__ __forceinline__ void cp_wait(int n) {
    switch (n) {
        case 0: asm volatile("cp.async.wait_group 0;" ::: "memory"); break;
        case 1: asm volatile("cp.async.wait_group 1;" ::: "memory"); break;
        case 2: asm volatile("cp.async.wait_group 2;" ::: "memory"); break;
        case 3: asm volatile("cp.async.wait_group 3;" ::: "memory"); break;
        case 4: asm volatile("cp.async.wait_group 4;" ::: "memory"); break;
        default: asm volatile("cp.async.wait_group 5;" ::: "memory"); break;
    }
}

__device__ __forceinline__ void cp_issue(unsigned int smem_dst, const float* gsrc) {
    asm volatile("cp.async.cg.shared.global [%0], [%1], 16;\n"
                 "cp.async.commit_group;\n" :: "r"(smem_dst), "l"(gsrc)
                 : "memory");
}

__global__ __launch_bounds__(256, 8) void embbag_mean_persistent(
    const int* __restrict__ indices,
    const int* __restrict__ offsets,
    const float* __restrict__ weights,
    float* __restrict__ out,
    int num_bags,            // T*B
    int bags_per_table,      // B
    int total_idx)           // T*B*L
{
    __shared__ __align__(16) float4 pipe_buf[WPB][STAGES][32];  // 24 KB

    const int lane = threadIdx.x & 31;
    const int wib  = threadIdx.x >> 5;
    const int warp_gid    = blockIdx.x * WPB + wib;
    const int total_warps = gridDim.x * WPB;

    int gw = warp_gid;
    if (gw >= num_bags) return;

    const int half    = lane >> 4;          // 0: even rows, 1: odd rows
    const int colbase = (lane & 15) << 2;   // float4 column offset
    const unsigned int sb =
        (unsigned int)__cvta_generic_to_shared(&pipe_buf[wib][0][lane]);

    // Preload first bag's metadata + index vector.
    int start = __ldg(offsets + gw);
    int end   = (gw == num_bags - 1) ? total_idx : __ldg(offsets + gw + 1);
    int count = end - start;
    int idx_l = (lane < 20 && count == 20) ? __ldg(indices + start + lane) : 0;

    for (;;) {
        // ---- Prefetch next bag (hidden under this bag's gathers) ----
        const int  gw_next   = gw + total_warps;
        const bool have_next = gw_next < num_bags;
        int start_n = 0, end_n = 0, count_n = 0, idx_l_n = 0;
        if (have_next) {
            start_n = __ldg(offsets + gw_next);
            end_n   = (gw_next == num_bags - 1) ? total_idx
                                                : __ldg(offsets + gw_next + 1);
            count_n = end_n - start_n;
            idx_l_n = (lane < 20 && count_n == 20)
                          ? __ldg(indices + start_n + lane) : 0;
        }

        // ---- Process current bag ----
        float4 acc = make_float4(0.f, 0.f, 0.f, 0.f);

        if (count == 20) {
            int r[10];
            #pragma unroll
            for (int it = 0; it < 10; ++it)
                r[it] = __shfl_sync(0xffffffffu, idx_l, 2 * it + half);

            #pragma unroll
            for (int s = 0; s < STAGES; ++s)
                cp_issue(sb + s * 512u,
                         weights + (size_t)r[s] * EMB_D + colbase);

            #pragma unroll
            for (int it = 0; it < 10; ++it) {
                cp_wait(min(STAGES - 1, 9 - it));
                float4 v = pipe_buf[wib][it % STAGES][lane];
                acc.x += v.x; acc.y += v.y; acc.z += v.z; acc.w += v.w;
                if (it + STAGES < 10)
                    cp_issue(sb + (it % STAGES) * 512u,
                             weights + (size_t)r[it + STAGES] * EMB_D + colbase);
            }
        } else {
            // Generic path (any bag length), plain gathers.
            for (int base = 0; base < count; base += 32) {
                int m = min(32, count - base);
                int il = (lane < m) ? __ldg(indices + start + base + lane) : 0;
                int it = 0;
                for (; it + 2 <= m; it += 2) {
                    int rr = __shfl_sync(0xffffffffu, il, it + half);
                    const float4 v = __ldg(reinterpret_cast<const float4*>(
                        weights + (size_t)rr * EMB_D + colbase));
                    acc.x += v.x; acc.y += v.y; acc.z += v.z; acc.w += v.w;
                }
                if (it < m) {
                    int rr = __shfl_sync(0xffffffffu, il, it);
                    if (half == 0) {
                        const float4 v = __ldg(reinterpret_cast<const float4*>(
                            weights + (size_t)rr * EMB_D + colbase));
                        acc.x += v.x; acc.y += v.y; acc.z += v.z; acc.w += v.w;
                    }
                }
            }
        }

        // Combine row-parity halves and store.
        acc.x += __shfl_xor_sync(0xffffffffu, acc.x, 16);
        acc.y += __shfl_xor_sync(0xffffffffu, acc.y, 16);
        acc.z += __shfl_xor_sync(0xffffffffu, acc.z, 16);
        acc.w += __shfl_xor_sync(0xffffffffu, acc.w, 16);

        if (half == 0) {
            int t = gw / bags_per_table;
            int b = gw - t * bags_per_table;
            float inv = 1.0f / fmaxf((float)count, 1.0f);
            float4 o = make_float4(acc.x * inv, acc.y * inv,
                                   acc.z * inv, acc.w * inv);
            *reinterpret_cast<float4*>(
                out + (size_t)b * (EMB_T * EMB_D) + t * EMB_D + colbase) = o;
        }

        if (!have_next) break;
        gw = gw_next; start = start_n; end = end_n;
        count = count_n; idx_l = idx_l_n;
    }
}

extern "C" void kernel_launch(void* const* d_in, const int* in_sizes, int n_in,
                              void* d_out, int out_size) {
    const int*   indices = (const int*)d_in[0];
    const int*   offsets = (const int*)d_in[1];
    const float* weights = (const float*)d_in[2];
    float*       out     = (float*)d_out;

    int num_bags       = in_sizes[1];          // T*B = 131072
    int bags_per_table = num_bags / EMB_T;     // B
    int total_idx      = in_sizes[0];          // T*B*L

    int blocks = PERSIST_BLOCKS;
    if (blocks * WPB > num_bags)
        blocks = (num_bags + WPB - 1) / WPB;

    embbag_mean_persistent<<<blocks, WPB * 32>>>(indices, offsets, weights, out,
                                                 num_bags, bags_per_table,
                                                 total_idx);
}

// round 7
// speedup vs baseline: 1.0884x; 1.0884x over previous
#include <cuda_runtime.h>
#include <cuda_bf16.h>
#include <cstdint>

// T=8 tables, N=500000 rows/table, D=64, B=16384 bags/table, L=20.
// indices [T*B*L] int32 (global row ids), offsets [T*B] int32,
// weights [T*N*D] f32. Output [B, T*D] f32.
//
// One warp per bag (R5 structure — best measured). lanes 0-15 -> even rows,
// lanes 16-31 -> odd rows, float4/lane => 512B per gather instruction.
// Gathers via cp.async.cg into a 6-deep smem ring (zero register residency
// in flight, L1 bypass). Output stored with st.global.cs (streaming) so
// dead write-once lines don't evict reusable table rows from L2.

#define EMB_D 64
#define EMB_T 8
#define STAGES 6

__device__ __forceinline__ void cp_wait(int n) {
    switch (n) {
        case 0: asm volatile("cp.async.wait_group 0;" ::: "memory"); break;
        case 1: asm volatile("cp.async.wait_group 1;" ::: "memory"); break;
        case 2: asm volatile("cp.async.wait_group 2;" ::: "memory"); break;
        case 3: asm volatile("cp.async.wait_group 3;" ::: "memory"); break;
        case 4: asm volatile("cp.async.wait_group 4;" ::: "memory"); break;
        default: asm volatile("cp.async.wait_group 5;" ::: "memory"); break;
    }
}

__device__ __forceinline__ void cp_issue(unsigned int smem_dst, const float* gsrc) {
    asm volatile("cp.async.cg.shared.global [%0], [%1], 16;\n"
                 "cp.async.commit_group;\n" :: "r"(smem_dst), "l"(gsrc)
                 : "memory");
}

__device__ __forceinline__ void stg_cs_v4(float* p, float4 v) {
    asm volatile("st.global.cs.v4.f32 [%0], {%1, %2, %3, %4};"
                 :: "l"(p), "f"(v.x), "f"(v.y), "f"(v.z), "f"(v.w)
                 : "memory");
}

__global__ __launch_bounds__(256, 8) void embbag_mean_kernel(
    const int* __restrict__ indices,
    const int* __restrict__ offsets,
    const float* __restrict__ weights,
    float* __restrict__ out,
    int num_bags,            // T*B
    int bags_per_table,      // B
    int idx_per_table)       // B*L
{
    __shared__ __align__(16) float4 pipe_buf[8][STAGES][32];  // 24 KB

    int gwarp = (blockIdx.x * blockDim.x + threadIdx.x) >> 5;
    int lane  = threadIdx.x & 31;
    int wib   = threadIdx.x >> 5;
    if (gwarp >= num_bags) return;

    int t = gwarp / bags_per_table;
    int b = gwarp - t * bags_per_table;

    int start = __ldg(offsets + gwarp);
    int end   = (b == bags_per_table - 1) ? (t + 1) * idx_per_table
                                          : __ldg(offsets + gwarp + 1);
    int count = end - start;

    const int half    = lane >> 4;          // 0: even rows, 1: odd rows
    const int colbase = (lane & 15) << 2;   // float4 column offset

    float4 acc = make_float4(0.f, 0.f, 0.f, 0.f);

    if (count == 20) {
        // One coalesced index load; broadcast my 10 row ids.
        int idx_l = (lane < 20) ? __ldg(indices + start + lane) : 0;
        int r[10];
        #pragma unroll
        for (int it = 0; it < 10; ++it)
            r[it] = __shfl_sync(0xffffffffu, idx_l, 2 * it + half);

        unsigned int sb =
            (unsigned int)__cvta_generic_to_shared(&pipe_buf[wib][0][lane]);
        // Prologue: fill the pipeline (6 gathers in flight, zero reg cost).
        #pragma unroll
        for (int s = 0; s < STAGES; ++s)
            cp_issue(sb + s * 512u, weights + (size_t)r[s] * EMB_D + colbase);

        #pragma unroll
        for (int it = 0; it < 10; ++it) {
            cp_wait(min(STAGES - 1, 9 - it));
            float4 v = pipe_buf[wib][it % STAGES][lane];
            acc.x += v.x; acc.y += v.y; acc.z += v.z; acc.w += v.w;
            if (it + STAGES < 10)
                cp_issue(sb + (it % STAGES) * 512u,
                         weights + (size_t)r[it + STAGES] * EMB_D + colbase);
        }
    } else {
        // Generic path (any bag length), plain gathers.
        for (int base = 0; base < count; base += 32) {
            int m = min(32, count - base);
            int idx_l = (lane < m) ? __ldg(indices + start + base + lane) : 0;
            int it = 0;
            for (; it + 2 <= m; it += 2) {
                int rr = __shfl_sync(0xffffffffu, idx_l, it + half);
                const float4 v = __ldg(reinterpret_cast<const float4*>(
                    weights + (size_t)rr * EMB_D + colbase));
                acc.x += v.x; acc.y += v.y; acc.z += v.z; acc.w += v.w;
            }
            if (it < m) {
                int rr = __shfl_sync(0xffffffffu, idx_l, it);
                if (half == 0) {
                    const float4 v = __ldg(reinterpret_cast<const float4*>(
                        weights + (size_t)rr * EMB_D + colbase));
                    acc.x += v.x; acc.y += v.y; acc.z += v.z; acc.w += v.w;
                }
            }
        }
    }

    // Combine the two row-parity halves (same columns in both halves).
    acc.x += __shfl_xor_sync(0xffffffffu, acc.x, 16);
    acc.y += __shfl_xor_sync(0xffffffffu, acc.y, 16);
    acc.z += __shfl_xor_sync(0xffffffffu, acc.z, 16);
    acc.w += __shfl_xor_sync(0xffffffffu, acc.w, 16);

    if (half == 0) {
        float inv = 1.0f / fmaxf((float)count, 1.0f);
        float4 o = make_float4(acc.x * inv, acc.y * inv, acc.z * inv, acc.w * inv);
        stg_cs_v4(out + (size_t)b * (EMB_T * EMB_D) + t * EMB_D + colbase, o);
    }
}

extern "C" void kernel_launch(void* const* d_in, const int* in_sizes, int n_in,
                              void* d_out, int out_size) {
    const int*   indices = (const int*)d_in[0];
    const int*   offsets = (const int*)d_in[1];
    const float* weights = (const float*)d_in[2];
    float*       out     = (float*)d_out;

    int num_bags       = in_sizes[1];          // T*B = 131072
    int bags_per_table = num_bags / EMB_T;     // B
    int idx_per_table  = in_sizes[0] / EMB_T;  // B*L

    int threads = 256;                          // 8 warps/block
    int total_threads = num_bags * 32;
    int blocks = (total_threads + threads - 1) / threads;

    embbag_mean_kernel<<<blocks, threads>>>(indices, offsets, weights, out,
                                            num_bags, bags_per_table,
                                            idx_per_table);
}